// round 6
// baseline (speedup 1.0000x reference)
#include <cuda_runtime.h>

// dims
#define B_ 64
#define N_ 32
#define F_ 16
#define S_ 8
#define C_ 128
#define H_ 256
#define D_ 256
#define OBS_STRIDE 9728
#define A_OFF 512        // N_*F_
#define E_OFF 1536       // N_*F_ + N_*N_
#define KAUG 4112        // (H_+1)*F_
#define KCHUNKS 257      // KAUG/16, exact
#define ROWS 2048        // B_*N_
#define KSPLIT 16

// phase1 batching
#define RPC 4            // rows per CTA
#define SLOTS 48         // edge slots per batch (NP=24 pairs)
#define NP 24
#define MAXSLOTS 144     // worst case 4*32=128, padded
#define H1T_STRIDE 52    // 48 slots + 4 pad (16B-aligned rows: 52*4=208, 208%16=0)

typedef unsigned long long ull;

// packed fp32x2 FMA (Blackwell FFMA2): d = a*b + c elementwise on 2 lanes
#define FMA2(d, a, b, c) \
    asm("fma.rn.f32x2 %0, %1, %2, %3;" : "=l"(d) : "l"(a), "l"(b), "l"(c))
#define PACK2(d, lo, hi)                                 \
    asm("mov.b64 %0, {%1, %2};"                          \
        : "=l"(d)                                        \
        : "r"(__float_as_uint(lo)), "r"(__float_as_uint(hi)))
#define UNPACK2(lo, hi, s) \
    asm("mov.b64 {%0, %1}, %2;" : "=r"(lo), "=r"(hi) : "l"(s))

// scratch (static device allocations; no runtime alloc)
__device__ __align__(16) float g_WkT[KAUG * C_];      // augmented Wk  [k=(h,f)][c]
__device__ __align__(16) float g_M[ROWS * KAUG];      // M[b*N+j][h*16+f]
__device__ __align__(16) float g_P[KSPLIT * ROWS * C_];
__device__ __align__(16) float g_Xc[ROWS * C_];       // post-conv node features

// ---------------------------------------------------------------------------
// Prep: build augmented WkT (Wk rows + bk row) in [k][c] layout
// ---------------------------------------------------------------------------
__global__ void prep_kernel(const float* __restrict__ Wk,
                            const float* __restrict__ bk) {
    int t = blockIdx.x * blockDim.x + threadIdx.x;
    if (t < KAUG * C_) {
        int k = t >> 7, c = t & 127;
        int h = k >> 4, f = k & 15;
        g_WkT[t] = (h < H_) ? Wk[h * (C_ * F_) + c * F_ + f] : bk[c * F_ + f];
    }
}

// ---------------------------------------------------------------------------
// Phase 1: 4 rows per CTA, flat compacted edge list across the 4 rows.
//   M[row][k][f] = sum_e relu(h2[e][k]+b2[k]) * X[e][f]; M[row][256][f]=sum X
// Flat list padded to 48-slot batches (NP=24 packed accumulators).
// Dynamic smem (floats):
//   h1T [256][52]  @ 0       (13312)  -- aliased as h2s[48][256] after h-loop
//   Xs  [144][16]  @ 13312   (2304)
//   Es  [144][8]   @ 15616   (1152)   total 16768 floats = 67072 B
// ---------------------------------------------------------------------------
#define P1_SMEM_BYTES (16768 * 4)

__global__ void __launch_bounds__(256) phase1_kernel(
    const float* __restrict__ obs,
    const float* __restrict__ W1,
    const float* __restrict__ b1,
    const float* __restrict__ W2,
    const float* __restrict__ b2) {
    extern __shared__ __align__(16) float sm[];
    float* h1T = sm;            // [h][slot-local], stride 52
    float* h2s = sm;            // alias: [slot-local][k], 48*256 <= 13312
    float* Xs  = sm + 13312;    // [flat slot][16]
    float* Es  = sm + 15616;    // [flat slot][8]
    __shared__ int edgeSrc[MAXSLOTS];
    __shared__ int edgeRow[MAXSLOTS];
    __shared__ int s_rowStart[RPC];
    __shared__ int s_cnt[RPC];
    __shared__ int s_total;

    const int tid = threadIdx.x;
    const int cta = blockIdx.x;                 // 0..511
    const int b = cta >> 3;
    const int j0 = (cta & 7) * RPC;
    const float* orow = obs + (size_t)b * OBS_STRIDE;

    // deterministic compaction of active columns for 4 rows (warp 0)
    if (tid < 32) {
        int base = 0;
#pragma unroll
        for (int r = 0; r < RPC; r++) {
            float a = orow[A_OFF + (j0 + r) * N_ + tid];
            unsigned m = __ballot_sync(0xffffffffu, a != 0.0f);
            int pos = __popc(m & ((1u << tid) - 1u));
            if (a != 0.0f) {
                edgeSrc[base + pos] = tid;
                edgeRow[base + pos] = r;
            }
            if (tid == 0) {
                s_rowStart[r] = base;
                s_cnt[r] = __popc(m);
            }
            base += __popc(m);
        }
        if (tid == 0) s_total = base;
    }
    __syncthreads();

    const int total = s_total;
    const int nbatch = (total + SLOTS - 1) / SLOTS;   // 0..3
    const int totSlots = nbatch * SLOTS;

    // gather X and E for flat slots; zero padding (X=0 kills padded slots)
    for (int t = tid; t < totSlots * F_; t += 256) {
        int e = t >> 4, f = t & 15;
        Xs[t] = (e < total) ? orow[edgeSrc[e] * F_ + f] : 0.0f;
    }
    for (int t = tid; t < totSlots * S_; t += 256) {
        int e = t >> 3, s = t & 7;
        Es[t] = (e < total)
                    ? orow[E_OFF + ((j0 + edgeRow[e]) * N_ + edgeSrc[e]) * S_ + s]
                    : 0.0f;
    }
    __syncthreads();

    const int k = tid;  // unit index (H_ == 256 == blockDim)

    float w1r[S_];
#pragma unroll
    for (int s = 0; s < S_; s++) w1r[s] = __ldg(&W1[s * H_ + k]);
    const float b1k = __ldg(&b1[k]);
    const float b2k = __ldg(&b2[k]);
    const float* w2col = W2 + k;

    for (int base = 0; base < totSlots; base += SLOTS) {
        // h1 = relu(E @ W1 + b1) for this batch, stored transposed [k][slot]
        for (int e = 0; e < SLOTS; e++) {
            float acc = b1k;
#pragma unroll
            for (int s = 0; s < S_; s++) acc += Es[(base + e) * S_ + s] * w1r[s];
            h1T[k * H1T_STRIDE + e] = fmaxf(acc, 0.0f);
        }
        __syncthreads();

        // h2 pre-activation via packed FFMA2, NP=24 pairs (48 slots)
        ull acc2[NP];
#pragma unroll
        for (int p = 0; p < NP; p++) acc2[p] = 0ull;

        for (int h0 = 0; h0 < H_; h0 += 8) {
            float w[8];
#pragma unroll
            for (int i = 0; i < 8; i++) w[i] = __ldg(&w2col[(h0 + i) * H_]);
#pragma unroll
            for (int i = 0; i < 8; i++) {
                ull ww;
                PACK2(ww, w[i], w[i]);
                const ulonglong2* hp = reinterpret_cast<const ulonglong2*>(
                    h1T + (h0 + i) * H1T_STRIDE);
#pragma unroll
                for (int q = 0; q < NP / 2; q++) {
                    ulonglong2 pv = hp[q];
                    FMA2(acc2[2 * q + 0], pv.x, ww, acc2[2 * q + 0]);
                    FMA2(acc2[2 * q + 1], pv.y, ww, acc2[2 * q + 1]);
                }
            }
        }
        __syncthreads();  // all h1T reads done before aliasing as h2s

        // write relu'd h2 to smem [slot][k]
#pragma unroll
        for (int p = 0; p < NP; p++) {
            unsigned u0, u1;
            UNPACK2(u0, u1, acc2[p]);
            h2s[(2 * p + 0) * H_ + k] = fmaxf(__uint_as_float(u0) + b2k, 0.0f);
            h2s[(2 * p + 1) * H_ + k] = fmaxf(__uint_as_float(u1) + b2k, 0.0f);
        }
        __syncthreads();

        // fold into M rows: M[r][k][f] += h2[e][k] * X[e][f]
        float Mloc[RPC][F_];
#pragma unroll
        for (int r = 0; r < RPC; r++)
#pragma unroll
            for (int f = 0; f < F_; f++) Mloc[r][f] = 0.0f;

#pragma unroll
        for (int r = 0; r < RPC; r++) {
            int lo = s_rowStart[r], hi = lo + s_cnt[r];
            if (lo < base) lo = base;
            if (hi > base + SLOTS) hi = base + SLOTS;
            for (int e = lo; e < hi; e++) {
                float h2v = h2s[(e - base) * H_ + k];
#pragma unroll
                for (int f = 0; f < F_; f++)
                    Mloc[r][f] += h2v * Xs[e * F_ + f];
            }
        }

        // commit to g_M (first batch overwrites; later batches accumulate)
#pragma unroll
        for (int r = 0; r < RPC; r++) {
            const int row = b * N_ + j0 + r;
            float* mrow = g_M + ((size_t)row * (H_ + 1) + k) * F_;
            if (base == 0) {
#pragma unroll
                for (int f = 0; f < F_; f += 4)
                    *reinterpret_cast<float4*>(mrow + f) = make_float4(
                        Mloc[r][f], Mloc[r][f + 1], Mloc[r][f + 2], Mloc[r][f + 3]);
            } else {
#pragma unroll
                for (int f = 0; f < F_; f += 4) {
                    float4 old = *reinterpret_cast<const float4*>(mrow + f);
                    *reinterpret_cast<float4*>(mrow + f) = make_float4(
                        old.x + Mloc[r][f], old.y + Mloc[r][f + 1],
                        old.z + Mloc[r][f + 2], old.w + Mloc[r][f + 3]);
                }
            }
        }
        __syncthreads();  // h2s reads done before next batch rewrites h1T
    }

    // handle total==0 (nbatch==0): write zero M rows
    if (nbatch == 0) {
#pragma unroll
        for (int r = 0; r < RPC; r++) {
            const int row = b * N_ + j0 + r;
            float* mrow = g_M + ((size_t)row * (H_ + 1) + k) * F_;
#pragma unroll
            for (int f = 0; f < F_; f += 4)
                *reinterpret_cast<float4*>(mrow + f) =
                    make_float4(0.f, 0.f, 0.f, 0.f);
        }
    }

    // ones-row (bias-path aggregation): per row, sum of active X
    if (tid < RPC * F_) {
        const int r = tid >> 4, f = tid & 15;
        float s = 0.0f;
        const int lo = s_rowStart[r], hi = lo + s_cnt[r];
        for (int e = lo; e < hi; e++) s += Xs[e * F_ + f];
        const int row = b * N_ + j0 + r;
        g_M[((size_t)row * (H_ + 1) + H_) * F_ + f] = s;
    }
}

// ---------------------------------------------------------------------------
// Phase 2: split-K GEMM with FFMA2 + register double-buffering.
// P[s][2048][128] partials of M[2048,4112] @ WkT[4112,128].
// 64x128x16 tile, 256 thr; microtile 4 rows (packed-broadcast A) x
// 8 cols (B column-pairs loaded directly as ulonglong2).
// ---------------------------------------------------------------------------
__global__ void __launch_bounds__(256) gemm_kernel() {
    __shared__ __align__(16) float As[16][68];   // transposed A tile (+pad)
    __shared__ __align__(16) float Bs[16][128];

    const int tid = threadIdx.x;
    const int tx = tid & 15, ty = tid >> 4;      // tx: 8 cols, ty: 4 rows
    const int r0 = blockIdx.x * 64;
    const int s = blockIdx.y;

    ull acc2[4][4];  // [row][col-pair]
#pragma unroll
    for (int r = 0; r < 4; r++)
#pragma unroll
        for (int cp = 0; cp < 4; cp++) acc2[r][cp] = 0ull;

    const int rrL = tid >> 2;            // A-load row 0..63
    const int kkL = (tid & 3) << 2;      // A-load k   0,4,8,12
    const int kkB = tid >> 5;            // B-load base k 0..7
    const int ccB = (tid & 31) << 2;     // B-load col

    int ch = s;
    float4 aP = *reinterpret_cast<const float4*>(
        &g_M[(size_t)(r0 + rrL) * KAUG + ch * 16 + kkL]);
    float4 bP0 = *reinterpret_cast<const float4*>(
        &g_WkT[(size_t)(ch * 16 + kkB) * C_ + ccB]);
    float4 bP1 = *reinterpret_cast<const float4*>(
        &g_WkT[(size_t)(ch * 16 + kkB + 8) * C_ + ccB]);

    while (true) {
        As[kkL + 0][rrL] = aP.x;
        As[kkL + 1][rrL] = aP.y;
        As[kkL + 2][rrL] = aP.z;
        As[kkL + 3][rrL] = aP.w;
        *reinterpret_cast<float4*>(&Bs[kkB][ccB]) = bP0;
        *reinterpret_cast<float4*>(&Bs[kkB + 8][ccB]) = bP1;
        __syncthreads();

        const int chn = ch + KSPLIT;
        const bool more = (chn < KCHUNKS);
        if (more) {
            aP = *reinterpret_cast<const float4*>(
                &g_M[(size_t)(r0 + rrL) * KAUG + chn * 16 + kkL]);
            bP0 = *reinterpret_cast<const float4*>(
                &g_WkT[(size_t)(chn * 16 + kkB) * C_ + ccB]);
            bP1 = *reinterpret_cast<const float4*>(
                &g_WkT[(size_t)(chn * 16 + kkB + 8) * C_ + ccB]);
        }

#pragma unroll
        for (int kk = 0; kk < 16; kk++) {
            float4 a = *reinterpret_cast<const float4*>(&As[kk][ty * 4]);
            ulonglong2 bq0 =
                *reinterpret_cast<const ulonglong2*>(&Bs[kk][tx * 8]);
            ulonglong2 bq1 =
                *reinterpret_cast<const ulonglong2*>(&Bs[kk][tx * 8 + 4]);
            ull aa[4];
            PACK2(aa[0], a.x, a.x);
            PACK2(aa[1], a.y, a.y);
            PACK2(aa[2], a.z, a.z);
            PACK2(aa[3], a.w, a.w);
            ull bv0 = bq0.x, bv1 = bq0.y, bv2 = bq1.x, bv3 = bq1.y;
#pragma unroll
            for (int r = 0; r < 4; r++) {
                FMA2(acc2[r][0], bv0, aa[r], acc2[r][0]);
                FMA2(acc2[r][1], bv1, aa[r], acc2[r][1]);
                FMA2(acc2[r][2], bv2, aa[r], acc2[r][2]);
                FMA2(acc2[r][3], bv3, aa[r], acc2[r][3]);
            }
        }
        if (!more) break;
        ch = chn;
        __syncthreads();
    }

    float* prow = g_P + ((size_t)s * ROWS + r0) * C_;
#pragma unroll
    for (int r = 0; r < 4; r++) {
        unsigned lo[8], hi[8];
#pragma unroll
        for (int cp = 0; cp < 4; cp++) UNPACK2(lo[cp], hi[cp], acc2[r][cp]);
        // acc2[r][cp] = (col 2cp, col 2cp+1)
        float4 o0 = make_float4(__uint_as_float(lo[0]), __uint_as_float(hi[0]),
                                __uint_as_float(lo[1]), __uint_as_float(hi[1]));
        float4 o1 = make_float4(__uint_as_float(lo[2]), __uint_as_float(hi[2]),
                                __uint_as_float(lo[3]), __uint_as_float(hi[3]));
        *reinterpret_cast<float4*>(&prow[(ty * 4 + r) * C_ + tx * 8]) = o0;
        *reinterpret_cast<float4*>(&prow[(ty * 4 + r) * C_ + tx * 8 + 4]) = o1;
    }
}

// ---------------------------------------------------------------------------
// Reduce: Xc[row][c] = relu( sum_s P[s][row][c] + X[row]@Wroot + bconv )
// ---------------------------------------------------------------------------
__global__ void __launch_bounds__(128) reduce_kernel(
    const float* __restrict__ obs,
    const float* __restrict__ Wroot,
    const float* __restrict__ bconv) {
    const int row = blockIdx.x;
    const int c = threadIdx.x;
    const int b = row >> 5, j = row & 31;

    float sum = bconv[c];
#pragma unroll
    for (int s = 0; s < KSPLIT; s++)
        sum += g_P[((size_t)s * ROWS + row) * C_ + c];

    const float* xr = obs + (size_t)b * OBS_STRIDE + j * F_;
#pragma unroll
    for (int f = 0; f < F_; f++) sum += xr[f] * Wroot[f * C_ + c];

    g_Xc[(size_t)row * C_ + c] = fmaxf(sum, 0.0f);
}

// ---------------------------------------------------------------------------
// Phase 3: per batch element — attention softmax pool + dense tanh
// ---------------------------------------------------------------------------
__global__ void __launch_bounds__(256) phase3_kernel(
    const float* __restrict__ attn_w,
    const float* __restrict__ Wd,
    const float* __restrict__ bd,
    float* __restrict__ out) {
    __shared__ __align__(16) float Xc[N_][C_];
    __shared__ float attn[N_];
    __shared__ float logits[N_];
    __shared__ float pooled[C_];

    const int b = blockIdx.x;
    const int tid = threadIdx.x;

#pragma unroll
    for (int l = 0; l < 4; l++) {
        int t = tid + l * 256;
        reinterpret_cast<float4*>(&Xc[0][0])[t] =
            reinterpret_cast<const float4*>(g_Xc + (size_t)b * N_ * C_)[t];
    }
    __syncthreads();

    const int w = tid >> 5, lane = tid & 31;
    const float aw0 = attn_w[lane], aw1 = attn_w[lane + 32];
    const float aw2 = attn_w[lane + 64], aw3 = attn_w[lane + 96];
    for (int j = w * 4; j < w * 4 + 4; j++) {
        float p = Xc[j][lane] * aw0 + Xc[j][lane + 32] * aw1 +
                  Xc[j][lane + 64] * aw2 + Xc[j][lane + 96] * aw3;
#pragma unroll
        for (int off = 16; off; off >>= 1) p += __shfl_xor_sync(0xffffffffu, p, off);
        if (lane == 0) logits[j] = p;
    }
    __syncthreads();

    if (tid < 32) {
        float l = logits[tid];
        float m = l;
#pragma unroll
        for (int off = 16; off; off >>= 1)
            m = fmaxf(m, __shfl_xor_sync(0xffffffffu, m, off));
        float e = expf(l - m);
        float ssum = e;
#pragma unroll
        for (int off = 16; off; off >>= 1) ssum += __shfl_xor_sync(0xffffffffu, ssum, off);
        attn[tid] = e / ssum;
    }
    __syncthreads();

    if (tid < C_) {
        float pc = 0.0f;
#pragma unroll
        for (int j = 0; j < N_; j++) pc += attn[j] * Xc[j][tid];
        pooled[tid] = pc;
    }
    __syncthreads();

    float sum = bd[tid];
#pragma unroll 8
    for (int cc = 0; cc < C_; cc++) sum += pooled[cc] * Wd[cc * D_ + tid];
    out[(size_t)b * D_ + tid] = tanhf(sum);
}

// ---------------------------------------------------------------------------
extern "C" void kernel_launch(void* const* d_in, const int* in_sizes, int n_in,
                              void* d_out, int out_size) {
    const float* obs    = (const float*)d_in[0];
    const float* W1     = (const float*)d_in[1];
    const float* b1     = (const float*)d_in[2];
    const float* W2     = (const float*)d_in[3];
    const float* b2     = (const float*)d_in[4];
    const float* Wk     = (const float*)d_in[5];
    const float* bk     = (const float*)d_in[6];
    const float* Wroot  = (const float*)d_in[7];
    const float* bconv  = (const float*)d_in[8];
    const float* attn_w = (const float*)d_in[9];
    const float* Wd     = (const float*)d_in[10];
    const float* bd     = (const float*)d_in[11];
    float* out = (float*)d_out;

    cudaFuncSetAttribute(phase1_kernel,
                         cudaFuncAttributeMaxDynamicSharedMemorySize,
                         P1_SMEM_BYTES);

    prep_kernel<<<(KAUG * C_ + 255) / 256, 256>>>(Wk, bk);
    phase1_kernel<<<ROWS / RPC, 256, P1_SMEM_BYTES>>>(obs, W1, b1, W2, b2);
    gemm_kernel<<<dim3(ROWS / 64, KSPLIT), 256>>>();
    reduce_kernel<<<ROWS, 128>>>(obs, Wroot, bconv);
    phase3_kernel<<<B_, 256>>>(attn_w, Wd, bd, out);
}

// round 8
// speedup vs baseline: 1.6533x; 1.6533x over previous
#include <cuda_runtime.h>
#include <cuda_bf16.h>
#include <cstdint>

// dims
#define B_ 64
#define N_ 32
#define F_ 16
#define S_ 8
#define C_ 128
#define H_ 256
#define D_ 256
#define OBS_STRIDE 9728
#define A_OFF 512        // N_*F_
#define E_OFF 1536       // N_*F_ + N_*N_
#define ROWS 2048        // B_*N_
#define EDGES 65536      // max edges
#define KAUG2 4160       // G2 K: 4096 (h,f) + 16 ones + 48 pad
#define KCH2 130         // KAUG2/32 chunks
#define KSPLIT 8
#define ASTR 40          // smem tile k-stride (bf16 elems), conflict-free

// warp-level bf16 MMA, fp32 accum (HMMA; compiles for compute_103)
#define MMA_BF16(c, a, b0v, b1v)                                        \
    asm volatile(                                                       \
        "mma.sync.aligned.m16n8k16.row.col.f32.bf16.bf16.f32 "          \
        "{%0,%1,%2,%3}, {%4,%5,%6,%7}, {%8,%9}, {%0,%1,%2,%3};"         \
        : "+f"((c)[0]), "+f"((c)[1]), "+f"((c)[2]), "+f"((c)[3])        \
        : "r"((a)[0]), "r"((a)[1]), "r"((a)[2]), "r"((a)[3]),           \
          "r"(b0v), "r"(b1v))

__device__ __forceinline__ void bsplit(float x, __nv_bfloat16& h, __nv_bfloat16& l) {
    h = __float2bfloat16(x);
    l = __float2bfloat16(x - __bfloat162float(h));
}

// ---------------------------------------------------------------------------
// static scratch
// ---------------------------------------------------------------------------
__device__ __align__(16) __nv_bfloat16 g_W2Thi[H_ * H_];   // W2T[c][k]
__device__ __align__(16) __nv_bfloat16 g_W2Tlo[H_ * H_];
__device__ __align__(16) __nv_bfloat16 g_B2hi[C_ * KAUG2]; // B2[c][kk]
__device__ __align__(16) __nv_bfloat16 g_B2lo[C_ * KAUG2];
__device__ __align__(16) __nv_bfloat16 g_h1hi[(size_t)EDGES * H_];
__device__ __align__(16) __nv_bfloat16 g_h1lo[(size_t)EDGES * H_];
__device__ __align__(16) float g_h2[(size_t)EDGES * H_];
__device__ __align__(16) __nv_bfloat16 g_A2hi[(size_t)ROWS * KAUG2];
__device__ __align__(16) __nv_bfloat16 g_A2lo[(size_t)ROWS * KAUG2];
__device__ __align__(16) float g_P[KSPLIT * ROWS * C_];
__device__ __align__(16) float g_Xc[ROWS * C_];
__device__ int g_cnt[ROWS];
__device__ int g_rowStart[ROWS];
__device__ int g_eSrc[EDGES];
__device__ int g_eRow[EDGES];
__device__ int g_meta[4];   // [0]=total, [1]=padTotal, [2]=ntiles

// ---------------------------------------------------------------------------
// prep: W2T bf16 pairs + augmented B2 bf16 pairs
// ---------------------------------------------------------------------------
__global__ void prep_kernel(const float* __restrict__ W2,
                            const float* __restrict__ Wk,
                            const float* __restrict__ bk) {
    int t = blockIdx.x * 256 + threadIdx.x;
    if (t < H_ * H_) {
        int c = t >> 8, k = t & 255;
        __nv_bfloat16 h, l;
        bsplit(W2[k * H_ + c], h, l);
        g_W2Thi[t] = h;
        g_W2Tlo[t] = l;
    }
    if (t < C_ * KAUG2) {
        int c = t / KAUG2, kk = t % KAUG2;
        float v = 0.0f;
        if (kk < 4096) v = Wk[(kk >> 4) * (C_ * F_) + c * F_ + (kk & 15)];
        else if (kk < 4112) v = bk[c * F_ + (kk - 4096)];
        __nv_bfloat16 h, l;
        bsplit(v, h, l);
        g_B2hi[t] = h;
        g_B2lo[t] = l;
    }
}

// ---------------------------------------------------------------------------
// count + scan: per-row active-edge counts, exclusive scan -> rowStart, total
// single CTA of 1024 threads (2 rows each), Hillis-Steele scan
// ---------------------------------------------------------------------------
__global__ void __launch_bounds__(1024) count_scan_kernel(const float* __restrict__ obs) {
    __shared__ int sA[1024], sB[1024];
    const int t = threadIdx.x;
    int c0 = 0, c1 = 0;
    {
        const int r0 = 2 * t, r1 = 2 * t + 1;
        const float* a0 = obs + (size_t)(r0 >> 5) * OBS_STRIDE + A_OFF + (r0 & 31) * N_;
        const float* a1 = obs + (size_t)(r1 >> 5) * OBS_STRIDE + A_OFF + (r1 & 31) * N_;
#pragma unroll 8
        for (int i = 0; i < N_; i++) {
            c0 += (a0[i] != 0.0f);
            c1 += (a1[i] != 0.0f);
        }
    }
    g_cnt[2 * t] = c0;
    g_cnt[2 * t + 1] = c1;
    const int pair = c0 + c1;
    sA[t] = pair;
    __syncthreads();
    int* src = sA;
    int* dst = sB;
    for (int off = 1; off < 1024; off <<= 1) {
        int v = src[t] + (t >= off ? src[t - off] : 0);
        dst[t] = v;
        __syncthreads();
        int* tmp = src; src = dst; dst = tmp;
    }
    const int inc = src[t];
    const int excl = inc - pair;
    g_rowStart[2 * t] = excl;
    g_rowStart[2 * t + 1] = excl + c0;
    if (t == 1023) {
        int total = inc;
        int ntiles = (total + 127) >> 7;
        g_meta[0] = total;
        g_meta[1] = ntiles << 7;
        g_meta[2] = ntiles;
    }
}

// ---------------------------------------------------------------------------
// fill: compact edge list (deterministic ballot order)
// ---------------------------------------------------------------------------
__global__ void __launch_bounds__(256) fill_kernel(const float* __restrict__ obs) {
    const int b = blockIdx.x;
    const int wid = threadIdx.x >> 5, lane = threadIdx.x & 31;
    const float* orow = obs + (size_t)b * OBS_STRIDE;
    for (int j = wid; j < N_; j += 8) {
        const int row = b * N_ + j;
        float a = orow[A_OFF + j * N_ + lane];
        unsigned m = __ballot_sync(0xffffffffu, a != 0.0f);
        int pos = __popc(m & ((1u << lane) - 1u));
        if (a != 0.0f) {
            int s = g_rowStart[row] + pos;
            g_eSrc[s] = lane;
            g_eRow[s] = row;
        }
    }
}

// ---------------------------------------------------------------------------
// h1: for active edge slots, h1 = relu(E @ W1 + b1) as bf16 pair [slot][k]
// grid 512 tiles (early exit), 256 threads (thread = k)
// ---------------------------------------------------------------------------
__global__ void __launch_bounds__(256) h1_kernel(const float* __restrict__ obs,
                                                 const float* __restrict__ W1,
                                                 const float* __restrict__ b1) {
    __shared__ float Es[128 * S_];
    const int tile = blockIdx.x;
    if (tile >= g_meta[2]) return;
    const int total = g_meta[0];
    const int base = tile << 7;
    const int limit = (total - base < 128) ? (total - base) : 128;
    const int tid = threadIdx.x;

    {
        const int slot = tid >> 1, q = (tid & 1) * 4;
        float4 v = make_float4(0.f, 0.f, 0.f, 0.f);
        if (slot < limit) {
            const int gs = base + slot;
            const int row = g_eRow[gs], i = g_eSrc[gs];
            const int b = row >> 5, j = row & 31;
            v = *reinterpret_cast<const float4*>(
                obs + (size_t)b * OBS_STRIDE + E_OFF + (size_t)(j * N_ + i) * S_ + q);
        }
        *reinterpret_cast<float4*>(&Es[slot * S_ + q]) = v;
    }
    __syncthreads();

    const int k = tid;
    float w1r[S_];
#pragma unroll
    for (int s = 0; s < S_; s++) w1r[s] = __ldg(&W1[s * H_ + k]);
    const float b1k = __ldg(&b1[k]);

    for (int e = 0; e < 128; e++) {
        float acc = b1k;
#pragma unroll
        for (int s = 0; s < S_; s++) acc += Es[e * S_ + s] * w1r[s];
        acc = (e < limit) ? fmaxf(acc, 0.0f) : 0.0f;
        __nv_bfloat16 h, l;
        bsplit(acc, h, l);
        const size_t o = (size_t)(base + e) * H_ + k;
        g_h1hi[o] = h;
        g_h1lo[o] = l;
    }
}

// ---------------------------------------------------------------------------
// G1: h2 = relu(h1 @ W2T^T + b2) via mma.sync bf16 3-pass.
// grid (512 tiles, 2 col-tiles), 256 thr = 8 warps (4x2), warp tile 32x64.
// ---------------------------------------------------------------------------
__global__ void __launch_bounds__(256) g1_mma_kernel(const float* __restrict__ b2) {
    __shared__ __nv_bfloat16 Ah[128 * ASTR], Al[128 * ASTR];
    __shared__ __nv_bfloat16 Bh[128 * ASTR], Bl[128 * ASTR];
    const int tile = blockIdx.x;
    if (tile >= g_meta[2]) return;
    const int c0 = blockIdx.y * 128;
    const int tid = threadIdx.x, wid = tid >> 5, lane = tid & 31;
    const int warpM = wid & 3, warpN = wid >> 2;
    const int g = lane >> 2, tig = lane & 3;

    float acc[2][8][4];
#pragma unroll
    for (int m = 0; m < 2; m++)
#pragma unroll
        for (int n = 0; n < 8; n++)
#pragma unroll
            for (int q = 0; q < 4; q++) acc[m][n][q] = 0.0f;

    const size_t abase = (size_t)tile * 128 * H_;

#pragma unroll 1
    for (int ch = 0; ch < 8; ch++) {
        const int k0 = ch * 32;
#pragma unroll
        for (int l = 0; l < 2; l++) {
            const int idx = tid + l * 256;
            const int r = idx >> 2, kq = (idx & 3) * 8;
            *reinterpret_cast<uint4*>(&Ah[r * ASTR + kq]) =
                *reinterpret_cast<const uint4*>(&g_h1hi[abase + (size_t)r * H_ + k0 + kq]);
            *reinterpret_cast<uint4*>(&Al[r * ASTR + kq]) =
                *reinterpret_cast<const uint4*>(&g_h1lo[abase + (size_t)r * H_ + k0 + kq]);
            *reinterpret_cast<uint4*>(&Bh[r * ASTR + kq]) =
                *reinterpret_cast<const uint4*>(&g_W2Thi[(size_t)(c0 + r) * H_ + k0 + kq]);
            *reinterpret_cast<uint4*>(&Bl[r * ASTR + kq]) =
                *reinterpret_cast<const uint4*>(&g_W2Tlo[(size_t)(c0 + r) * H_ + k0 + kq]);
        }
        __syncthreads();

#pragma unroll
        for (int kw = 0; kw < 32; kw += 16) {
            uint32_t ah[2][4], al[2][4];
#pragma unroll
            for (int m = 0; m < 2; m++) {
                const int rb = warpM * 32 + m * 16;
                ah[m][0] = *reinterpret_cast<uint32_t*>(&Ah[(rb + g) * ASTR + kw + tig * 2]);
                ah[m][1] = *reinterpret_cast<uint32_t*>(&Ah[(rb + g + 8) * ASTR + kw + tig * 2]);
                ah[m][2] = *reinterpret_cast<uint32_t*>(&Ah[(rb + g) * ASTR + kw + tig * 2 + 8]);
                ah[m][3] = *reinterpret_cast<uint32_t*>(&Ah[(rb + g + 8) * ASTR + kw + tig * 2 + 8]);
                al[m][0] = *reinterpret_cast<uint32_t*>(&Al[(rb + g) * ASTR + kw + tig * 2]);
                al[m][1] = *reinterpret_cast<uint32_t*>(&Al[(rb + g + 8) * ASTR + kw + tig * 2]);
                al[m][2] = *reinterpret_cast<uint32_t*>(&Al[(rb + g) * ASTR + kw + tig * 2 + 8]);
                al[m][3] = *reinterpret_cast<uint32_t*>(&Al[(rb + g + 8) * ASTR + kw + tig * 2 + 8]);
            }
#pragma unroll
            for (int n = 0; n < 8; n++) {
                const int cb = warpN * 64 + n * 8;
                uint32_t bh0 = *reinterpret_cast<uint32_t*>(&Bh[(cb + g) * ASTR + kw + tig * 2]);
                uint32_t bh1 = *reinterpret_cast<uint32_t*>(&Bh[(cb + g) * ASTR + kw + tig * 2 + 8]);
                uint32_t bl0 = *reinterpret_cast<uint32_t*>(&Bl[(cb + g) * ASTR + kw + tig * 2]);
                uint32_t bl1 = *reinterpret_cast<uint32_t*>(&Bl[(cb + g) * ASTR + kw + tig * 2 + 8]);
#pragma unroll
                for (int m = 0; m < 2; m++) {
                    MMA_BF16(acc[m][n], ah[m], bh0, bh1);
                    MMA_BF16(acc[m][n], ah[m], bl0, bl1);
                    MMA_BF16(acc[m][n], al[m], bh0, bh1);
                }
            }
        }
        __syncthreads();
    }

    // epilogue: +b2, relu, store fp32 h2
#pragma unroll
    for (int n = 0; n < 8; n++) {
        const int col = c0 + warpN * 64 + n * 8 + tig * 2;
        const float bias0 = __ldg(&b2[col]), bias1 = __ldg(&b2[col + 1]);
#pragma unroll
        for (int m = 0; m < 2; m++) {
            const int r0 = tile * 128 + warpM * 32 + m * 16 + g;
            float2 v0 = make_float2(fmaxf(acc[m][n][0] + bias0, 0.0f),
                                    fmaxf(acc[m][n][1] + bias1, 0.0f));
            float2 v1 = make_float2(fmaxf(acc[m][n][2] + bias0, 0.0f),
                                    fmaxf(acc[m][n][3] + bias1, 0.0f));
            *reinterpret_cast<float2*>(&g_h2[(size_t)r0 * H_ + col]) = v0;
            *reinterpret_cast<float2*>(&g_h2[(size_t)(r0 + 8) * H_ + col]) = v1;
        }
    }
}

// ---------------------------------------------------------------------------
// fold: A2[row][kk] (bf16 pair) = sum over this row's edge slots of h2*X
// grid 2048 rows, 256 thr (thread = h)
// ---------------------------------------------------------------------------
__global__ void __launch_bounds__(256) fold_kernel(const float* __restrict__ obs) {
    __shared__ float Xs[N_ * F_];
    __shared__ int idx[N_];
    __shared__ int s_start, s_cnt;
    const int row = blockIdx.x;
    const int b = row >> 5;
    const int k = threadIdx.x;
    const float* orow = obs + (size_t)b * OBS_STRIDE;

    if (k == 0) {
        s_start = g_rowStart[row];
        s_cnt = g_cnt[row];
    }
    for (int t = k; t < N_ * F_; t += 256) Xs[t] = orow[t];
    __syncthreads();
    const int cnt = s_cnt, start = s_start;
    if (k < cnt) idx[k] = g_eSrc[start + k];
    __syncthreads();

    float M[F_];
#pragma unroll
    for (int f = 0; f < F_; f++) M[f] = 0.0f;

    for (int e = 0; e < cnt; e++) {
        const float h2v = g_h2[(size_t)(start + e) * H_ + k];
        const int i = idx[e];
#pragma unroll
        for (int f = 0; f < F_; f++) M[f] += h2v * Xs[i * F_ + f];
    }

    __align__(16) __nv_bfloat16 hi[F_], lo[F_];
#pragma unroll
    for (int f = 0; f < F_; f++) bsplit(M[f], hi[f], lo[f]);
    {
        const size_t o = (size_t)row * KAUG2 + k * F_;
        reinterpret_cast<uint4*>(g_A2hi + o)[0] = reinterpret_cast<uint4*>(hi)[0];
        reinterpret_cast<uint4*>(g_A2hi + o)[1] = reinterpret_cast<uint4*>(hi)[1];
        reinterpret_cast<uint4*>(g_A2lo + o)[0] = reinterpret_cast<uint4*>(lo)[0];
        reinterpret_cast<uint4*>(g_A2lo + o)[1] = reinterpret_cast<uint4*>(lo)[1];
    }

    // ones-row (kk 4096..4111) + zero pad (4112..4159)
    if (k < 16) {
        float ssum = 0.0f;
        for (int e = 0; e < cnt; e++) ssum += Xs[idx[e] * F_ + k];
        __nv_bfloat16 h, l;
        bsplit(ssum, h, l);
        g_A2hi[(size_t)row * KAUG2 + 4096 + k] = h;
        g_A2lo[(size_t)row * KAUG2 + 4096 + k] = l;
    } else if (k < 64) {
        g_A2hi[(size_t)row * KAUG2 + 4096 + k] = __float2bfloat16(0.0f);
        g_A2lo[(size_t)row * KAUG2 + 4096 + k] = __float2bfloat16(0.0f);
    }
}

// ---------------------------------------------------------------------------
// G2: P[s] partial of A2[2048,4160] @ B2^T via mma.sync bf16 3-pass
// grid (16 row-tiles, 8 splits), 256 thr, same warp layout (N=128)
// ---------------------------------------------------------------------------
__global__ void __launch_bounds__(256) g2_mma_kernel() {
    __shared__ __nv_bfloat16 Ah[128 * ASTR], Al[128 * ASTR];
    __shared__ __nv_bfloat16 Bh[128 * ASTR], Bl[128 * ASTR];
    const int r0 = blockIdx.x * 128;
    const int s = blockIdx.y;
    const int tid = threadIdx.x, wid = tid >> 5, lane = tid & 31;
    const int warpM = wid & 3, warpN = wid >> 2;
    const int g = lane >> 2, tig = lane & 3;

    float acc[2][8][4];
#pragma unroll
    for (int m = 0; m < 2; m++)
#pragma unroll
        for (int n = 0; n < 8; n++)
#pragma unroll
            for (int q = 0; q < 4; q++) acc[m][n][q] = 0.0f;

#pragma unroll 1
    for (int ch = s; ch < KCH2; ch += KSPLIT) {
        const int k0 = ch * 32;
#pragma unroll
        for (int l = 0; l < 2; l++) {
            const int idx = tid + l * 256;
            const int r = idx >> 2, kq = (idx & 3) * 8;
            *reinterpret_cast<uint4*>(&Ah[r * ASTR + kq]) =
                *reinterpret_cast<const uint4*>(&g_A2hi[(size_t)(r0 + r) * KAUG2 + k0 + kq]);
            *reinterpret_cast<uint4*>(&Al[r * ASTR + kq]) =
                *reinterpret_cast<const uint4*>(&g_A2lo[(size_t)(r0 + r) * KAUG2 + k0 + kq]);
            *reinterpret_cast<uint4*>(&Bh[r * ASTR + kq]) =
                *reinterpret_cast<const uint4*>(&g_B2hi[(size_t)r * KAUG2 + k0 + kq]);
            *reinterpret_cast<uint4*>(&Bl[r * ASTR + kq]) =
                *reinterpret_cast<const uint4*>(&g_B2lo[(size_t)r * KAUG2 + k0 + kq]);
        }
        __syncthreads();

#pragma unroll
        for (int kw = 0; kw < 32; kw += 16) {
            uint32_t ah[2][4], al[2][4];
#pragma unroll
            for (int m = 0; m < 2; m++) {
                const int rb = warpM * 32 + m * 16;
                ah[m][0] = *reinterpret_cast<uint32_t*>(&Ah[(rb + g) * ASTR + kw + tig * 2]);
                ah[m][1] = *reinterpret_cast<uint32_t*>(&Ah[(rb + g + 8) * ASTR + kw + tig * 2]);
                ah[m][2] = *reinterpret_cast<uint32_t*>(&Ah[(rb + g) * ASTR + kw + tig * 2 + 8]);
                ah[m][3] = *reinterpret_cast<uint32_t*>(&Ah[(rb + g + 8) * ASTR + kw + tig * 2 + 8]);
                al[m][0] = *reinterpret_cast<uint32_t*>(&Al[(rb + g) * ASTR + kw + tig * 2]);
                al[m][1] = *reinterpret_cast<uint32_t*>(&Al[(rb + g + 8) * ASTR + kw + tig * 2]);
                al[m][2] = *reinterpret_cast<uint32_t*>(&Al[(rb + g) * ASTR + kw + tig * 2 + 8]);
                al[m][3] = *reinterpret_cast<uint32_t*>(&Al[(rb + g + 8) * ASTR + kw + tig * 2 + 8]);
            }
#pragma unroll
            for (int n = 0; n < 8; n++) {
                const int cb = warpN * 64 + n * 8;
                uint32_t bh0 = *reinterpret_cast<uint32_t*>(&Bh[(cb + g) * ASTR + kw + tig * 2]);
                uint32_t bh1 = *reinterpret_cast<uint32_t*>(&Bh[(cb + g) * ASTR + kw + tig * 2 + 8]);
                uint32_t bl0 = *reinterpret_cast<uint32_t*>(&Bl[(cb + g) * ASTR + kw + tig * 2]);
                uint32_t bl1 = *reinterpret_cast<uint32_t*>(&Bl[(cb + g) * ASTR + kw + tig * 2 + 8]);
#pragma unroll
                for (int m = 0; m < 2; m++) {
                    MMA_BF16(acc[m][n], ah[m], bh0, bh1);
                    MMA_BF16(acc[m][n], ah[m], bl0, bl1);
                    MMA_BF16(acc[m][n], al[m], bh0, bh1);
                }
            }
        }
        __syncthreads();
    }

#pragma unroll
    for (int n = 0; n < 8; n++) {
        const int col = warpN * 64 + n * 8 + tig * 2;
#pragma unroll
        for (int m = 0; m < 2; m++) {
            const int rr = r0 + warpM * 32 + m * 16 + g;
            float2 v0 = make_float2(acc[m][n][0], acc[m][n][1]);
            float2 v1 = make_float2(acc[m][n][2], acc[m][n][3]);
            *reinterpret_cast<float2*>(&g_P[((size_t)s * ROWS + rr) * C_ + col]) = v0;
            *reinterpret_cast<float2*>(&g_P[((size_t)s * ROWS + rr + 8) * C_ + col]) = v1;
        }
    }
}

// ---------------------------------------------------------------------------
// reduce: Xc[row][c] = relu( sum_s P[s][row][c] + X[row]@Wroot + bconv )
// ---------------------------------------------------------------------------
__global__ void __launch_bounds__(128) reduce_kernel(
    const float* __restrict__ obs,
    const float* __restrict__ Wroot,
    const float* __restrict__ bconv) {
    const int row = blockIdx.x;
    const int c = threadIdx.x;
    const int b = row >> 5, j = row & 31;

    float sum = bconv[c];
#pragma unroll
    for (int s = 0; s < KSPLIT; s++)
        sum += g_P[((size_t)s * ROWS + row) * C_ + c];

    const float* xr = obs + (size_t)b * OBS_STRIDE + j * F_;
#pragma unroll
    for (int f = 0; f < F_; f++) sum += xr[f] * Wroot[f * C_ + c];

    g_Xc[(size_t)row * C_ + c] = fmaxf(sum, 0.0f);
}

// ---------------------------------------------------------------------------
// phase3: attention softmax pool + dense tanh
// ---------------------------------------------------------------------------
__global__ void __launch_bounds__(256) phase3_kernel(
    const float* __restrict__ attn_w,
    const float* __restrict__ Wd,
    const float* __restrict__ bd,
    float* __restrict__ out) {
    __shared__ __align__(16) float Xc[N_][C_];
    __shared__ float attn[N_];
    __shared__ float logits[N_];
    __shared__ float pooled[C_];

    const int b = blockIdx.x;
    const int tid = threadIdx.x;

#pragma unroll
    for (int l = 0; l < 4; l++) {
        int t = tid + l * 256;
        reinterpret_cast<float4*>(&Xc[0][0])[t] =
            reinterpret_cast<const float4*>(g_Xc + (size_t)b * N_ * C_)[t];
    }
    __syncthreads();

    const int w = tid >> 5, lane = tid & 31;
    const float aw0 = attn_w[lane], aw1 = attn_w[lane + 32];
    const float aw2 = attn_w[lane + 64], aw3 = attn_w[lane + 96];
    for (int j = w * 4; j < w * 4 + 4; j++) {
        float p = Xc[j][lane] * aw0 + Xc[j][lane + 32] * aw1 +
                  Xc[j][lane + 64] * aw2 + Xc[j][lane + 96] * aw3;
#pragma unroll
        for (int off = 16; off; off >>= 1) p += __shfl_xor_sync(0xffffffffu, p, off);
        if (lane == 0) logits[j] = p;
    }
    __syncthreads();

    if (tid < 32) {
        float l = logits[tid];
        float m = l;
#pragma unroll
        for (int off = 16; off; off >>= 1)
            m = fmaxf(m, __shfl_xor_sync(0xffffffffu, m, off));
        float e = expf(l - m);
        float ssum = e;
#pragma unroll
        for (int off = 16; off; off >>= 1) ssum += __shfl_xor_sync(0xffffffffu, ssum, off);
        attn[tid] = e / ssum;
    }
    __syncthreads();

    if (tid < C_) {
        float pc = 0.0f;
#pragma unroll
        for (int j = 0; j < N_; j++) pc += attn[j] * Xc[j][tid];
        pooled[tid] = pc;
    }
    __syncthreads();

    float sum = bd[tid];
#pragma unroll 8
    for (int cc = 0; cc < C_; cc++) sum += pooled[cc] * Wd[cc * D_ + tid];
    out[(size_t)b * D_ + tid] = tanhf(sum);
}

// ---------------------------------------------------------------------------
extern "C" void kernel_launch(void* const* d_in, const int* in_sizes, int n_in,
                              void* d_out, int out_size) {
    const float* obs    = (const float*)d_in[0];
    const float* W1     = (const float*)d_in[1];
    const float* b1     = (const float*)d_in[2];
    const float* W2     = (const float*)d_in[3];
    const float* b2     = (const float*)d_in[4];
    const float* Wk     = (const float*)d_in[5];
    const float* bk     = (const float*)d_in[6];
    const float* Wroot  = (const float*)d_in[7];
    const float* bconv  = (const float*)d_in[8];
    const float* attn_w = (const float*)d_in[9];
    const float* Wd     = (const float*)d_in[10];
    const float* bd     = (const float*)d_in[11];
    float* out = (float*)d_out;

    prep_kernel<<<(C_ * KAUG2 + 255) / 256, 256>>>(W2, Wk, bk);
    count_scan_kernel<<<1, 1024>>>(obs);
    fill_kernel<<<B_, 256>>>(obs);
    h1_kernel<<<512, 256>>>(obs, W1, b1);
    g1_mma_kernel<<<dim3(512, 2), 256>>>(b2);
    fold_kernel<<<ROWS, 256>>>(obs);
    g2_mma_kernel<<<dim3(16, KSPLIT), 256>>>();
    reduce_kernel<<<ROWS, 128>>>(obs, Wroot, bconv);
    phase3_kernel<<<B_, 256>>>(attn_w, Wd, bd, out);
}

// round 9
// speedup vs baseline: 1.7440x; 1.0548x over previous
#include <cuda_runtime.h>
#include <cuda_bf16.h>
#include <cstdint>

// dims
#define B_ 64
#define N_ 32
#define F_ 16
#define S_ 8
#define C_ 128
#define H_ 256
#define D_ 256
#define OBS_STRIDE 9728
#define A_OFF 512        // N_*F_
#define E_OFF 1536       // N_*F_ + N_*N_
#define ROWS 2048        // B_*N_
#define EDGES 65536      // max edges
#define KAUG2 4160       // G2 K: 4096 (h,f) + 16 ones + 48 pad
#define KCH2 65          // KAUG2/64 chunks
#define KSPLIT 8
#define ASTR 72          // smem tile k-stride (bf16), 64 + 8 pad, conflict-free frags

// warp-level bf16 MMA, fp32 accum (HMMA; compiles for compute_103)
#define MMA_BF16(c, a, b0v, b1v)                                        \
    asm volatile(                                                       \
        "mma.sync.aligned.m16n8k16.row.col.f32.bf16.bf16.f32 "          \
        "{%0,%1,%2,%3}, {%4,%5,%6,%7}, {%8,%9}, {%0,%1,%2,%3};"         \
        : "+f"((c)[0]), "+f"((c)[1]), "+f"((c)[2]), "+f"((c)[3])        \
        : "r"((a)[0]), "r"((a)[1]), "r"((a)[2]), "r"((a)[3]),           \
          "r"(b0v), "r"(b1v))

__device__ __forceinline__ void bsplit(float x, __nv_bfloat16& h, __nv_bfloat16& l) {
    h = __float2bfloat16(x);
    l = __float2bfloat16(x - __bfloat162float(h));
}

// ---------------------------------------------------------------------------
// static scratch
// ---------------------------------------------------------------------------
__device__ __align__(16) __nv_bfloat16 g_W2Thi[H_ * H_];   // W2T[c][k]
__device__ __align__(16) __nv_bfloat16 g_W2Tlo[H_ * H_];
__device__ __align__(16) __nv_bfloat16 g_B2hi[C_ * KAUG2]; // B2[c][kk]
__device__ __align__(16) __nv_bfloat16 g_B2lo[C_ * KAUG2];
__device__ __align__(16) __nv_bfloat16 g_h1hi[(size_t)EDGES * H_];
__device__ __align__(16) __nv_bfloat16 g_h1lo[(size_t)EDGES * H_];
__device__ __align__(16) float g_h2[(size_t)EDGES * H_];
__device__ __align__(16) __nv_bfloat16 g_A2hi[(size_t)ROWS * KAUG2];
__device__ __align__(16) __nv_bfloat16 g_A2lo[(size_t)ROWS * KAUG2];
__device__ __align__(16) float g_P[KSPLIT * ROWS * C_];
__device__ __align__(16) float g_Xc[ROWS * C_];
__device__ int g_cnt[ROWS];
__device__ int g_rowStart[ROWS];
__device__ int g_eSrc[EDGES];
__device__ int g_eRow[EDGES];
__device__ int g_meta[4];   // [0]=total, [1]=padTotal, [2]=ntiles

// dyn smem layout for MMA kernels (bf16 elem offsets); 4 x 128 x 72 x 2B = 73728B
#define TILE_ELEMS (128 * ASTR)
#define MMA_SMEM_BYTES (4 * TILE_ELEMS * 2)

// ---------------------------------------------------------------------------
// prep: W2T bf16 pairs + augmented B2 bf16 pairs
// ---------------------------------------------------------------------------
__global__ void prep_kernel(const float* __restrict__ W2,
                            const float* __restrict__ Wk,
                            const float* __restrict__ bk) {
    int t = blockIdx.x * 256 + threadIdx.x;
    if (t < H_ * H_) {
        int c = t >> 8, k = t & 255;
        __nv_bfloat16 h, l;
        bsplit(W2[k * H_ + c], h, l);
        g_W2Thi[t] = h;
        g_W2Tlo[t] = l;
    }
    if (t < C_ * KAUG2) {
        int c = t / KAUG2, kk = t % KAUG2;
        float v = 0.0f;
        if (kk < 4096) v = Wk[(kk >> 4) * (C_ * F_) + c * F_ + (kk & 15)];
        else if (kk < 4112) v = bk[c * F_ + (kk - 4096)];
        __nv_bfloat16 h, l;
        bsplit(v, h, l);
        g_B2hi[t] = h;
        g_B2lo[t] = l;
    }
}

// ---------------------------------------------------------------------------
// count + scan (single CTA, 1024 thr, 2 rows each)
// ---------------------------------------------------------------------------
__global__ void __launch_bounds__(1024) count_scan_kernel(const float* __restrict__ obs) {
    __shared__ int sA[1024], sB[1024];
    const int t = threadIdx.x;
    int c0 = 0, c1 = 0;
    {
        const int r0 = 2 * t, r1 = 2 * t + 1;
        const float* a0 = obs + (size_t)(r0 >> 5) * OBS_STRIDE + A_OFF + (r0 & 31) * N_;
        const float* a1 = obs + (size_t)(r1 >> 5) * OBS_STRIDE + A_OFF + (r1 & 31) * N_;
#pragma unroll 8
        for (int i = 0; i < N_; i++) {
            c0 += (a0[i] != 0.0f);
            c1 += (a1[i] != 0.0f);
        }
    }
    g_cnt[2 * t] = c0;
    g_cnt[2 * t + 1] = c1;
    const int pair = c0 + c1;
    sA[t] = pair;
    __syncthreads();
    int* src = sA;
    int* dst = sB;
    for (int off = 1; off < 1024; off <<= 1) {
        int v = src[t] + (t >= off ? src[t - off] : 0);
        dst[t] = v;
        __syncthreads();
        int* tmp = src; src = dst; dst = tmp;
    }
    const int inc = src[t];
    const int excl = inc - pair;
    g_rowStart[2 * t] = excl;
    g_rowStart[2 * t + 1] = excl + c0;
    if (t == 1023) {
        int total = inc;
        int ntiles = (total + 127) >> 7;
        g_meta[0] = total;
        g_meta[1] = ntiles << 7;
        g_meta[2] = ntiles;
    }
}

// ---------------------------------------------------------------------------
// fill: compact edge list (deterministic ballot order)
// ---------------------------------------------------------------------------
__global__ void __launch_bounds__(256) fill_kernel(const float* __restrict__ obs) {
    const int b = blockIdx.x;
    const int wid = threadIdx.x >> 5, lane = threadIdx.x & 31;
    const float* orow = obs + (size_t)b * OBS_STRIDE;
    for (int j = wid; j < N_; j += 8) {
        const int row = b * N_ + j;
        float a = orow[A_OFF + j * N_ + lane];
        unsigned m = __ballot_sync(0xffffffffu, a != 0.0f);
        int pos = __popc(m & ((1u << lane) - 1u));
        if (a != 0.0f) {
            int s = g_rowStart[row] + pos;
            g_eSrc[s] = lane;
            g_eRow[s] = row;
        }
    }
}

// ---------------------------------------------------------------------------
// h1: grid (512 tiles, 4 quarters) — 32 slots per CTA, thread = k
// ---------------------------------------------------------------------------
__global__ void __launch_bounds__(256) h1_kernel(const float* __restrict__ obs,
                                                 const float* __restrict__ W1,
                                                 const float* __restrict__ b1) {
    __shared__ float Es[32 * S_];
    const int tile = blockIdx.x;
    if (tile >= g_meta[2]) return;
    const int total = g_meta[0];
    const int base = (tile << 7) + blockIdx.y * 32;
    int limit = total - base;
    if (limit > 32) limit = 32;
    if (limit < 0) limit = 0;
    const int tid = threadIdx.x;

    if (tid < 64) {
        const int slot = tid >> 1, q = (tid & 1) * 4;
        float4 v = make_float4(0.f, 0.f, 0.f, 0.f);
        if (slot < limit) {
            const int gs = base + slot;
            const int row = g_eRow[gs], i = g_eSrc[gs];
            const int b = row >> 5, j = row & 31;
            v = *reinterpret_cast<const float4*>(
                obs + (size_t)b * OBS_STRIDE + E_OFF + (size_t)(j * N_ + i) * S_ + q);
        }
        *reinterpret_cast<float4*>(&Es[slot * S_ + q]) = v;
    }
    __syncthreads();

    const int k = tid;
    float w1r[S_];
#pragma unroll
    for (int s = 0; s < S_; s++) w1r[s] = __ldg(&W1[s * H_ + k]);
    const float b1k = __ldg(&b1[k]);

    for (int e = 0; e < 32; e++) {
        float acc = b1k;
#pragma unroll
        for (int s = 0; s < S_; s++) acc += Es[e * S_ + s] * w1r[s];
        acc = (e < limit) ? fmaxf(acc, 0.0f) : 0.0f;
        __nv_bfloat16 h, l;
        bsplit(acc, h, l);
        const size_t o = (size_t)(base + e) * H_ + k;
        g_h1hi[o] = h;
        g_h1lo[o] = l;
    }
}

// ---------------------------------------------------------------------------
// G1: h2 = relu(h1 @ W2T^T + b2), mma.sync bf16 3-pass, K-chunk 64.
// grid (512 tiles, 2 col-tiles), 256 thr = 8 warps (4Mx2N), warp tile 32x64.
// ---------------------------------------------------------------------------
__global__ void __launch_bounds__(256) g1_mma_kernel(const float* __restrict__ b2) {
    extern __shared__ __align__(16) __nv_bfloat16 smem[];
    __nv_bfloat16* Ah = smem;
    __nv_bfloat16* Al = smem + TILE_ELEMS;
    __nv_bfloat16* Bh = smem + 2 * TILE_ELEMS;
    __nv_bfloat16* Bl = smem + 3 * TILE_ELEMS;
    const int tile = blockIdx.x;
    if (tile >= g_meta[2]) return;
    const int c0 = blockIdx.y * 128;
    const int tid = threadIdx.x, wid = tid >> 5, lane = tid & 31;
    const int warpM = wid & 3, warpN = wid >> 2;
    const int g = lane >> 2, tig = lane & 3;

    float acc[2][8][4];
#pragma unroll
    for (int m = 0; m < 2; m++)
#pragma unroll
        for (int n = 0; n < 8; n++)
#pragma unroll
            for (int q = 0; q < 4; q++) acc[m][n][q] = 0.0f;

    const size_t abase = (size_t)tile * 128 * H_;

#pragma unroll 1
    for (int ch = 0; ch < 4; ch++) {
        const int k0 = ch * 64;
#pragma unroll
        for (int l = 0; l < 4; l++) {
            const int idx = tid + l * 256;
            const int r = idx >> 3, kq = (idx & 7) * 8;
            *reinterpret_cast<uint4*>(&Ah[r * ASTR + kq]) =
                *reinterpret_cast<const uint4*>(&g_h1hi[abase + (size_t)r * H_ + k0 + kq]);
            *reinterpret_cast<uint4*>(&Al[r * ASTR + kq]) =
                *reinterpret_cast<const uint4*>(&g_h1lo[abase + (size_t)r * H_ + k0 + kq]);
            *reinterpret_cast<uint4*>(&Bh[r * ASTR + kq]) =
                *reinterpret_cast<const uint4*>(&g_W2Thi[(size_t)(c0 + r) * H_ + k0 + kq]);
            *reinterpret_cast<uint4*>(&Bl[r * ASTR + kq]) =
                *reinterpret_cast<const uint4*>(&g_W2Tlo[(size_t)(c0 + r) * H_ + k0 + kq]);
        }
        __syncthreads();

#pragma unroll
        for (int kw = 0; kw < 64; kw += 16) {
            uint32_t ah[2][4], al[2][4];
#pragma unroll
            for (int m = 0; m < 2; m++) {
                const int rb = warpM * 32 + m * 16;
                ah[m][0] = *reinterpret_cast<uint32_t*>(&Ah[(rb + g) * ASTR + kw + tig * 2]);
                ah[m][1] = *reinterpret_cast<uint32_t*>(&Ah[(rb + g + 8) * ASTR + kw + tig * 2]);
                ah[m][2] = *reinterpret_cast<uint32_t*>(&Ah[(rb + g) * ASTR + kw + tig * 2 + 8]);
                ah[m][3] = *reinterpret_cast<uint32_t*>(&Ah[(rb + g + 8) * ASTR + kw + tig * 2 + 8]);
                al[m][0] = *reinterpret_cast<uint32_t*>(&Al[(rb + g) * ASTR + kw + tig * 2]);
                al[m][1] = *reinterpret_cast<uint32_t*>(&Al[(rb + g + 8) * ASTR + kw + tig * 2]);
                al[m][2] = *reinterpret_cast<uint32_t*>(&Al[(rb + g) * ASTR + kw + tig * 2 + 8]);
                al[m][3] = *reinterpret_cast<uint32_t*>(&Al[(rb + g + 8) * ASTR + kw + tig * 2 + 8]);
            }
#pragma unroll
            for (int n = 0; n < 8; n++) {
                const int cb = warpN * 64 + n * 8;
                uint32_t bh0 = *reinterpret_cast<uint32_t*>(&Bh[(cb + g) * ASTR + kw + tig * 2]);
                uint32_t bh1 = *reinterpret_cast<uint32_t*>(&Bh[(cb + g) * ASTR + kw + tig * 2 + 8]);
                uint32_t bl0 = *reinterpret_cast<uint32_t*>(&Bl[(cb + g) * ASTR + kw + tig * 2]);
                uint32_t bl1 = *reinterpret_cast<uint32_t*>(&Bl[(cb + g) * ASTR + kw + tig * 2 + 8]);
#pragma unroll
                for (int m = 0; m < 2; m++) {
                    MMA_BF16(acc[m][n], ah[m], bh0, bh1);
                    MMA_BF16(acc[m][n], ah[m], bl0, bl1);
                    MMA_BF16(acc[m][n], al[m], bh0, bh1);
                }
            }
        }
        __syncthreads();
    }

#pragma unroll
    for (int n = 0; n < 8; n++) {
        const int col = c0 + warpN * 64 + n * 8 + tig * 2;
        const float bias0 = __ldg(&b2[col]), bias1 = __ldg(&b2[col + 1]);
#pragma unroll
        for (int m = 0; m < 2; m++) {
            const int r0 = tile * 128 + warpM * 32 + m * 16 + g;
            float2 v0 = make_float2(fmaxf(acc[m][n][0] + bias0, 0.0f),
                                    fmaxf(acc[m][n][1] + bias1, 0.0f));
            float2 v1 = make_float2(fmaxf(acc[m][n][2] + bias0, 0.0f),
                                    fmaxf(acc[m][n][3] + bias1, 0.0f));
            *reinterpret_cast<float2*>(&g_h2[(size_t)r0 * H_ + col]) = v0;
            *reinterpret_cast<float2*>(&g_h2[(size_t)(r0 + 8) * H_ + col]) = v1;
        }
    }
}

// ---------------------------------------------------------------------------
// fold: A2[row][kk] (bf16 pair) = sum over this row's edge slots of h2*X
// grid 2048 rows, 256 thr (thread = h); 4-wide h2 prefetch
// ---------------------------------------------------------------------------
__global__ void __launch_bounds__(256) fold_kernel(const float* __restrict__ obs) {
    __shared__ float Xs[N_ * F_];
    __shared__ int idx[N_];
    __shared__ int s_start, s_cnt;
    const int row = blockIdx.x;
    const int b = row >> 5;
    const int k = threadIdx.x;
    const float* orow = obs + (size_t)b * OBS_STRIDE;

    if (k == 0) {
        s_start = g_rowStart[row];
        s_cnt = g_cnt[row];
    }
    for (int t = k; t < N_ * F_; t += 256) Xs[t] = orow[t];
    __syncthreads();
    const int cnt = s_cnt, start = s_start;
    if (k < cnt) idx[k] = g_eSrc[start + k];
    __syncthreads();

    float M[F_];
#pragma unroll
    for (int f = 0; f < F_; f++) M[f] = 0.0f;

    const float* h2p = g_h2 + (size_t)start * H_ + k;
    int e = 0;
    for (; e + 4 <= cnt; e += 4) {
        const float v0 = h2p[(size_t)(e + 0) * H_];
        const float v1 = h2p[(size_t)(e + 1) * H_];
        const float v2 = h2p[(size_t)(e + 2) * H_];
        const float v3 = h2p[(size_t)(e + 3) * H_];
        const int i0 = idx[e], i1 = idx[e + 1], i2 = idx[e + 2], i3 = idx[e + 3];
#pragma unroll
        for (int f = 0; f < F_; f++) {
            M[f] += v0 * Xs[i0 * F_ + f];
            M[f] += v1 * Xs[i1 * F_ + f];
            M[f] += v2 * Xs[i2 * F_ + f];
            M[f] += v3 * Xs[i3 * F_ + f];
        }
    }
    for (; e < cnt; e++) {
        const float h2v = h2p[(size_t)e * H_];
        const int i = idx[e];
#pragma unroll
        for (int f = 0; f < F_; f++) M[f] += h2v * Xs[i * F_ + f];
    }

    __align__(16) __nv_bfloat16 hi[F_], lo[F_];
#pragma unroll
    for (int f = 0; f < F_; f++) bsplit(M[f], hi[f], lo[f]);
    {
        const size_t o = (size_t)row * KAUG2 + k * F_;
        reinterpret_cast<uint4*>(g_A2hi + o)[0] = reinterpret_cast<uint4*>(hi)[0];
        reinterpret_cast<uint4*>(g_A2hi + o)[1] = reinterpret_cast<uint4*>(hi)[1];
        reinterpret_cast<uint4*>(g_A2lo + o)[0] = reinterpret_cast<uint4*>(lo)[0];
        reinterpret_cast<uint4*>(g_A2lo + o)[1] = reinterpret_cast<uint4*>(lo)[1];
    }

    // ones-row (kk 4096..4111) + zero pad (4112..4159)
    if (k < 16) {
        float ssum = 0.0f;
        for (int ee = 0; ee < cnt; ee++) ssum += Xs[idx[ee] * F_ + k];
        __nv_bfloat16 h, l;
        bsplit(ssum, h, l);
        g_A2hi[(size_t)row * KAUG2 + 4096 + k] = h;
        g_A2lo[(size_t)row * KAUG2 + 4096 + k] = l;
    } else if (k < 64) {
        g_A2hi[(size_t)row * KAUG2 + 4096 + k] = __float2bfloat16(0.0f);
        g_A2lo[(size_t)row * KAUG2 + 4096 + k] = __float2bfloat16(0.0f);
    }
}

// ---------------------------------------------------------------------------
// G2: P[s] partial of A2[2048,4160] @ B2^T, K-chunk 64
// grid (16 row-tiles, 8 splits), 256 thr, same warp layout
// ---------------------------------------------------------------------------
__global__ void __launch_bounds__(256) g2_mma_kernel() {
    extern __shared__ __align__(16) __nv_bfloat16 smem[];
    __nv_bfloat16* Ah = smem;
    __nv_bfloat16* Al = smem + TILE_ELEMS;
    __nv_bfloat16* Bh = smem + 2 * TILE_ELEMS;
    __nv_bfloat16* Bl = smem + 3 * TILE_ELEMS;
    const int r0 = blockIdx.x * 128;
    const int s = blockIdx.y;
    const int tid = threadIdx.x, wid = tid >> 5, lane = tid & 31;
    const int warpM = wid & 3, warpN = wid >> 2;
    const int g = lane >> 2, tig = lane & 3;

    float acc[2][8][4];
#pragma unroll
    for (int m = 0; m < 2; m++)
#pragma unroll
        for (int n = 0; n < 8; n++)
#pragma unroll
            for (int q = 0; q < 4; q++) acc[m][n][q] = 0.0f;

#pragma unroll 1
    for (int ch = s; ch < KCH2; ch += KSPLIT) {
        const int k0 = ch * 64;
#pragma unroll
        for (int l = 0; l < 4; l++) {
            const int idx = tid + l * 256;
            const int r = idx >> 3, kq = (idx & 7) * 8;
            *reinterpret_cast<uint4*>(&Ah[r * ASTR + kq]) =
                *reinterpret_cast<const uint4*>(&g_A2hi[(size_t)(r0 + r) * KAUG2 + k0 + kq]);
            *reinterpret_cast<uint4*>(&Al[r * ASTR + kq]) =
                *reinterpret_cast<const uint4*>(&g_A2lo[(size_t)(r0 + r) * KAUG2 + k0 + kq]);
            *reinterpret_cast<uint4*>(&Bh[r * ASTR + kq]) =
                *reinterpret_cast<const uint4*>(&g_B2hi[(size_t)r * KAUG2 + k0 + kq]);
            *reinterpret_cast<uint4*>(&Bl[r * ASTR + kq]) =
                *reinterpret_cast<const uint4*>(&g_B2lo[(size_t)r * KAUG2 + k0 + kq]);
        }
        __syncthreads();

#pragma unroll
        for (int kw = 0; kw < 64; kw += 16) {
            uint32_t ah[2][4], al[2][4];
#pragma unroll
            for (int m = 0; m < 2; m++) {
                const int rb = warpM * 32 + m * 16;
                ah[m][0] = *reinterpret_cast<uint32_t*>(&Ah[(rb + g) * ASTR + kw + tig * 2]);
                ah[m][1] = *reinterpret_cast<uint32_t*>(&Ah[(rb + g + 8) * ASTR + kw + tig * 2]);
                ah[m][2] = *reinterpret_cast<uint32_t*>(&Ah[(rb + g) * ASTR + kw + tig * 2 + 8]);
                ah[m][3] = *reinterpret_cast<uint32_t*>(&Ah[(rb + g + 8) * ASTR + kw + tig * 2 + 8]);
                al[m][0] = *reinterpret_cast<uint32_t*>(&Al[(rb + g) * ASTR + kw + tig * 2]);
                al[m][1] = *reinterpret_cast<uint32_t*>(&Al[(rb + g + 8) * ASTR + kw + tig * 2]);
                al[m][2] = *reinterpret_cast<uint32_t*>(&Al[(rb + g) * ASTR + kw + tig * 2 + 8]);
                al[m][3] = *reinterpret_cast<uint32_t*>(&Al[(rb + g + 8) * ASTR + kw + tig * 2 + 8]);
            }
#pragma unroll
            for (int n = 0; n < 8; n++) {
                const int cb = warpN * 64 + n * 8;
                uint32_t bh0 = *reinterpret_cast<uint32_t*>(&Bh[(cb + g) * ASTR + kw + tig * 2]);
                uint32_t bh1 = *reinterpret_cast<uint32_t*>(&Bh[(cb + g) * ASTR + kw + tig * 2 + 8]);
                uint32_t bl0 = *reinterpret_cast<uint32_t*>(&Bl[(cb + g) * ASTR + kw + tig * 2]);
                uint32_t bl1 = *reinterpret_cast<uint32_t*>(&Bl[(cb + g) * ASTR + kw + tig * 2 + 8]);
#pragma unroll
                for (int m = 0; m < 2; m++) {
                    MMA_BF16(acc[m][n], ah[m], bh0, bh1);
                    MMA_BF16(acc[m][n], ah[m], bl0, bl1);
                    MMA_BF16(acc[m][n], al[m], bh0, bh1);
                }
            }
        }
        __syncthreads();
    }

#pragma unroll
    for (int n = 0; n < 8; n++) {
        const int col = warpN * 64 + n * 8 + tig * 2;
#pragma unroll
        for (int m = 0; m < 2; m++) {
            const int rr = r0 + warpM * 32 + m * 16 + g;
            float2 v0 = make_float2(acc[m][n][0], acc[m][n][1]);
            float2 v1 = make_float2(acc[m][n][2], acc[m][n][3]);
            *reinterpret_cast<float2*>(&g_P[((size_t)s * ROWS + rr) * C_ + col]) = v0;
            *reinterpret_cast<float2*>(&g_P[((size_t)s * ROWS + rr + 8) * C_ + col]) = v1;
        }
    }
}

// ---------------------------------------------------------------------------
// reduce: Xc[row][c] = relu( sum_s P[s][row][c] + X[row]@Wroot + bconv )
// ---------------------------------------------------------------------------
__global__ void __launch_bounds__(128) reduce_kernel(
    const float* __restrict__ obs,
    const float* __restrict__ Wroot,
    const float* __restrict__ bconv) {
    const int row = blockIdx.x;
    const int c = threadIdx.x;
    const int b = row >> 5, j = row & 31;

    float sum = bconv[c];
#pragma unroll
    for (int s = 0; s < KSPLIT; s++)
        sum += g_P[((size_t)s * ROWS + row) * C_ + c];

    const float* xr = obs + (size_t)b * OBS_STRIDE + j * F_;
#pragma unroll
    for (int f = 0; f < F_; f++) sum += xr[f] * Wroot[f * C_ + c];

    g_Xc[(size_t)row * C_ + c] = fmaxf(sum, 0.0f);
}

// ---------------------------------------------------------------------------
// phase3: attention softmax pool + dense tanh
// ---------------------------------------------------------------------------
__global__ void __launch_bounds__(256) phase3_kernel(
    const float* __restrict__ attn_w,
    const float* __restrict__ Wd,
    const float* __restrict__ bd,
    float* __restrict__ out) {
    __shared__ __align__(16) float Xc[N_][C_];
    __shared__ float attn[N_];
    __shared__ float logits[N_];
    __shared__ float pooled[C_];

    const int b = blockIdx.x;
    const int tid = threadIdx.x;

#pragma unroll
    for (int l = 0; l < 4; l++) {
        int t = tid + l * 256;
        reinterpret_cast<float4*>(&Xc[0][0])[t] =
            reinterpret_cast<const float4*>(g_Xc + (size_t)b * N_ * C_)[t];
    }
    __syncthreads();

    const int w = tid >> 5, lane = tid & 31;
    const float aw0 = attn_w[lane], aw1 = attn_w[lane + 32];
    const float aw2 = attn_w[lane + 64], aw3 = attn_w[lane + 96];
    for (int j = w * 4; j < w * 4 + 4; j++) {
        float p = Xc[j][lane] * aw0 + Xc[j][lane + 32] * aw1 +
                  Xc[j][lane + 64] * aw2 + Xc[j][lane + 96] * aw3;
#pragma unroll
        for (int off = 16; off; off >>= 1) p += __shfl_xor_sync(0xffffffffu, p, off);
        if (lane == 0) logits[j] = p;
    }
    __syncthreads();

    if (tid < 32) {
        float l = logits[tid];
        float m = l;
#pragma unroll
        for (int off = 16; off; off >>= 1)
            m = fmaxf(m, __shfl_xor_sync(0xffffffffu, m, off));
        float e = expf(l - m);
        float ssum = e;
#pragma unroll
        for (int off = 16; off; off >>= 1) ssum += __shfl_xor_sync(0xffffffffu, ssum, off);
        attn[tid] = e / ssum;
    }
    __syncthreads();

    if (tid < C_) {
        float pc = 0.0f;
#pragma unroll
        for (int j = 0; j < N_; j++) pc += attn[j] * Xc[j][tid];
        pooled[tid] = pc;
    }
    __syncthreads();

    float sum = bd[tid];
#pragma unroll 8
    for (int cc = 0; cc < C_; cc++) sum += pooled[cc] * Wd[cc * D_ + tid];
    out[(size_t)b * D_ + tid] = tanhf(sum);
}

// ---------------------------------------------------------------------------
extern "C" void kernel_launch(void* const* d_in, const int* in_sizes, int n_in,
                              void* d_out, int out_size) {
    const float* obs    = (const float*)d_in[0];
    const float* W1     = (const float*)d_in[1];
    const float* b1     = (const float*)d_in[2];
    const float* W2     = (const float*)d_in[3];
    const float* b2     = (const float*)d_in[4];
    const float* Wk     = (const float*)d_in[5];
    const float* bk     = (const float*)d_in[6];
    const float* Wroot  = (const float*)d_in[7];
    const float* bconv  = (const float*)d_in[8];
    const float* attn_w = (const float*)d_in[9];
    const float* Wd     = (const float*)d_in[10];
    const float* bd     = (const float*)d_in[11];
    float* out = (float*)d_out;

    cudaFuncSetAttribute(g1_mma_kernel,
                         cudaFuncAttributeMaxDynamicSharedMemorySize, MMA_SMEM_BYTES);
    cudaFuncSetAttribute(g2_mma_kernel,
                         cudaFuncAttributeMaxDynamicSharedMemorySize, MMA_SMEM_BYTES);

    prep_kernel<<<(C_ * KAUG2 + 255) / 256, 256>>>(W2, Wk, bk);
    count_scan_kernel<<<1, 1024>>>(obs);
    fill_kernel<<<B_, 256>>>(obs);
    h1_kernel<<<dim3(512, 4), 256>>>(obs, W1, b1);
    g1_mma_kernel<<<dim3(512, 2), 256, MMA_SMEM_BYTES>>>(b2);
    fold_kernel<<<ROWS, 256>>>(obs);
    g2_mma_kernel<<<dim3(16, KSPLIT), 256, MMA_SMEM_BYTES>>>();
    reduce_kernel<<<ROWS, 128>>>(obs, Wroot, bconv);
    phase3_kernel<<<B_, 256>>>(attn_w, Wd, bd, out);
}